// round 3
// baseline (speedup 1.0000x reference)
#include <cuda_runtime.h>

// Problem constants
#define NIMG 16
#define CIN 128
#define HDIM 64
#define WDIM 64
#define BTOT (NIMG*WDIM)      // 1024
#define OQKV 256
#define NGROUP 8
#define GPV 16                // OUT_PLANES / GROUPS
#define BNEPS 1e-5f

// ---------------- scratch (static __device__, no allocation) ----------------
// NOTE: 16B alignment is load-bearing — these are accessed through float4*.
__device__ __align__(16) float g_xt [BTOT * CIN * HDIM];     // [b][c][h]
__device__ __align__(16) float g_qkv[BTOT * OQKV * HDIM];    // [b][o][h]
__device__ __align__(16) float g_att[BTOT * 128 * HDIM];     // [b][p][h]
__device__ __align__(16) float g_weff[OQKV * CIN];           // BN-folded weights
__device__ float g_bias[OQKV];
__device__ float g_sc  [OQKV];
__device__ float g_aqk[NGROUP], g_aqr[NGROUP], g_akr[NGROUP];
__device__ float g_ae[128], g_ao[128], g_bs[128];

// ---------------- prep: fold all BN params ----------------
// bn_qkv: (4,256) -> gamma[0:256] beta[256:512] mean[512:768] var[768:1024]
// bn_sim: (4,24)  -> gamma[0:24]  beta[24:48]   mean[48:72]   var[72:96]
// bn_out: (4,256) -> gamma[0:256] beta[256:512] mean[512:768] var[768:1024]
__global__ void prep_params(const float* __restrict__ bnq,
                            const float* __restrict__ bns,
                            const float* __restrict__ bno) {
    int t = threadIdx.x;
    if (t < 256) {
        float ga = bnq[t], be = bnq[256 + t], m = bnq[512 + t], v = bnq[768 + t];
        float s = ga * rsqrtf(v + BNEPS);
        g_sc[t]  = s;
        g_bias[t] = be - s * m;
    }
    if (t < 24) {
        float s = bns[t] * rsqrtf(bns[72 + t] + BNEPS);
        if (t < 8)       g_aqk[t]      = s;
        else if (t < 16) g_aqr[t - 8]  = s;
        else             g_akr[t - 16] = s;
    }
    if (t < 128) {
        // out channel o = 2*p + e  (e=0: sv-part, e=1: sve-part), p = g*16+c
        int c0 = 2 * t, c1 = 2 * t + 1;
        float s0 = bno[c0] * rsqrtf(bno[768 + c0] + BNEPS);
        float s1 = bno[c1] * rsqrtf(bno[768 + c1] + BNEPS);
        g_ae[t] = s0;
        g_ao[t] = s1;
        g_bs[t] = (bno[256 + c0] - s0 * bno[512 + c0])
                + (bno[256 + c1] - s1 * bno[512 + c1]);
    }
}

__global__ void prep_weff(const float* __restrict__ w) {
    int o = blockIdx.x;           // 256
    int k = threadIdx.x;          // 128
    g_weff[o * 128 + k] = w[o * 128 + k] * g_sc[o];
}

// ---------------- transpose x: (n,c,h,w) -> xt[b=(n,w)][c][h] ----------------
__global__ void tr_x(const float* __restrict__ x) {
    __shared__ float tile[32][33];
    int nc = blockIdx.z;               // n*128 + c
    int n = nc >> 7, c = nc & 127;
    int h0 = blockIdx.x * 32, w0 = blockIdx.y * 32;
    const float* src = x + ((size_t)(n * 128 + c)) * 4096;
    #pragma unroll
    for (int y = threadIdx.y; y < 32; y += 8)
        tile[y][threadIdx.x] = src[(h0 + y) * 64 + w0 + threadIdx.x];
    __syncthreads();
    #pragma unroll
    for (int y = threadIdx.y; y < 32; y += 8)
        g_xt[((size_t)((n * 64 + (w0 + y)) * 128 + c)) * 64 + h0 + threadIdx.x]
            = tile[threadIdx.x][y];
}

// ---------------- QKV GEMM: qkv[b][o][h] = w_eff[o,:]·xt[b,:,h] + bias[o] ----
__global__ void __launch_bounds__(256) qkv_gemm() {
    __shared__ __align__(16) float xs[128 * 64];     // [c][h]
    __shared__ __align__(16) float wt[8][256];       // [kk][o]
    int b = blockIdx.x;
    int t = threadIdx.x;

    {   // load x tile (coalesced float4)
        const float4* src = (const float4*)(g_xt + (size_t)b * 8192);
        float4* dst = (float4*)xs;
        #pragma unroll
        for (int i = 0; i < 8; i++) dst[t + i * 256] = src[t + i * 256];
    }

    float acc[8][8];
    #pragma unroll
    for (int a = 0; a < 8; a++)
        #pragma unroll
        for (int bb = 0; bb < 8; bb++) acc[a][bb] = 0.f;

    int o0 = (t & 31) * 8;     // lane -> 8 output rows
    int h0 = (t >> 5) * 8;     // warp -> 8 h columns

    for (int kc = 0; kc < 16; kc++) {
        __syncthreads();
        const float4* wsrc = (const float4*)(g_weff + t * 128 + kc * 8);
        float4 wa = wsrc[0], wb = wsrc[1];
        wt[0][t] = wa.x; wt[1][t] = wa.y; wt[2][t] = wa.z; wt[3][t] = wa.w;
        wt[4][t] = wb.x; wt[5][t] = wb.y; wt[6][t] = wb.z; wt[7][t] = wb.w;
        __syncthreads();
        #pragma unroll
        for (int kk = 0; kk < 8; kk++) {
            int k = kc * 8 + kk;
            float4 xa = *(const float4*)&xs[k * 64 + h0];
            float4 xb = *(const float4*)&xs[k * 64 + h0 + 4];
            float4 va = *(const float4*)&wt[kk][o0];
            float4 vb = *(const float4*)&wt[kk][o0 + 4];
            float xr[8] = {xa.x, xa.y, xa.z, xa.w, xb.x, xb.y, xb.z, xb.w};
            float wr[8] = {va.x, va.y, va.z, va.w, vb.x, vb.y, vb.z, vb.w};
            #pragma unroll
            for (int oo = 0; oo < 8; oo++)
                #pragma unroll
                for (int hh = 0; hh < 8; hh++)
                    acc[oo][hh] += wr[oo] * xr[hh];
        }
    }

    float* outp = g_qkv + (size_t)b * 16384;
    #pragma unroll
    for (int oo = 0; oo < 8; oo++) {
        float bias = g_bias[o0 + oo];
        float4 r0, r1;
        r0.x = acc[oo][0] + bias; r0.y = acc[oo][1] + bias;
        r0.z = acc[oo][2] + bias; r0.w = acc[oo][3] + bias;
        r1.x = acc[oo][4] + bias; r1.y = acc[oo][5] + bias;
        r1.z = acc[oo][6] + bias; r1.w = acc[oo][7] + bias;
        *(float4*)&outp[(o0 + oo) * 64 + h0]     = r0;
        *(float4*)&outp[(o0 + oo) * 64 + h0 + 4] = r1;
    }
}

// ---------------- attention per (b, g) ----------------
__global__ void __launch_bounds__(256) attn(const float* __restrict__ rel) {
    int bx = blockIdx.x;
    int g = bx & 7;
    int b = bx >> 3;

    __shared__ __align__(16) float qs[8 * 64];       // scaled by a_qk
    __shared__ __align__(16) float ks[8 * 64];
    __shared__ __align__(16) float vT[64 * 17];      // [h][c]
    __shared__ __align__(16) float Rq[8 * 128];      // scaled by a_qr/a_qk
    __shared__ __align__(16) float Rk[8 * 128];      // scaled by a_kr
    __shared__ __align__(16) float RvT[127 * 17];    // [d][c]
    __shared__ __align__(16) float L[64 * 68];       // logits -> probabilities
    __shared__ float aes[16], aos[16], bss[16];

    int t = threadIdx.x;
    float aqk = g_aqk[g];
    float rqs = g_aqr[g] / aqk;
    float akr = g_akr[g];

    const float* qkvb = g_qkv + (size_t)b * 16384 + g * 32 * 64;

    for (int idx = t; idx < 1024; idx += 256) {
        int c = idx >> 6, h = idx & 63;
        float val = qkvb[idx];
        if (c < 8) qs[c * 64 + h] = val * aqk;
        else       ks[(c - 8) * 64 + h] = val;
    }
    for (int idx = t; idx < 1024; idx += 256) {
        int c = idx >> 6, h = idx & 63;
        vT[h * 17 + c] = qkvb[1024 + idx];
    }
    for (int idx = t; idx < 1016; idx += 256) {
        int c = idx / 127, d = idx % 127;
        Rq[c * 128 + d] = rel[c * 127 + d] * rqs;
        Rk[c * 128 + d] = rel[(8 + c) * 127 + d] * akr;
    }
    for (int idx = t; idx < 2032; idx += 256) {
        int c = idx / 127, d = idx % 127;
        RvT[d * 17 + c] = rel[(16 + c) * 127 + d];
    }
    if (t < 16) {
        int p = g * 16 + t;
        aes[t] = g_ae[p]; aos[t] = g_ao[p]; bss[t] = g_bs[p];
    }
    __syncthreads();

    // ---- logits: 4x4 tile per thread ----
    {
        int ti = t & 15, tj = t >> 4;
        int i0 = ti * 4, j0 = tj * 4;
        int dbase = i0 - j0 + 60;   // for Rq (d = i-j+63)
        int ebase = j0 - i0 + 60;   // for Rk (e = j-i+63)
        float acc[4][4];
        #pragma unroll
        for (int a = 0; a < 4; a++)
            #pragma unroll
            for (int bb = 0; bb < 4; bb++) acc[a][bb] = 0.f;

        #pragma unroll
        for (int c = 0; c < 8; c++) {
            float qv[4], kv[4], rq[7], rk[7];
            #pragma unroll
            for (int ii = 0; ii < 4; ii++) qv[ii] = qs[c * 64 + i0 + ii];
            #pragma unroll
            for (int jj = 0; jj < 4; jj++) kv[jj] = ks[c * 64 + j0 + jj];
            #pragma unroll
            for (int x = 0; x < 7; x++) rq[x] = Rq[c * 128 + dbase + x];
            #pragma unroll
            for (int x = 0; x < 7; x++) rk[x] = Rk[c * 128 + ebase + x];
            #pragma unroll
            for (int ii = 0; ii < 4; ii++)
                #pragma unroll
                for (int jj = 0; jj < 4; jj++)
                    acc[ii][jj] += qv[ii] * (kv[jj] + rq[ii - jj + 3])
                                 + kv[jj] * rk[jj - ii + 3];
        }
        #pragma unroll
        for (int ii = 0; ii < 4; ii++) {
            float4 r;
            r.x = acc[ii][0]; r.y = acc[ii][1]; r.z = acc[ii][2]; r.w = acc[ii][3];
            *(float4*)&L[(i0 + ii) * 68 + j0] = r;
        }
    }
    __syncthreads();

    // ---- softmax over j, per row ----
    {
        int w = t >> 5, lane = t & 31;
        for (int r = w * 8; r < w * 8 + 8; r++) {
            float x1 = L[r * 68 + lane], x2 = L[r * 68 + 32 + lane];
            float m = fmaxf(x1, x2);
            #pragma unroll
            for (int off = 16; off > 0; off >>= 1)
                m = fmaxf(m, __shfl_xor_sync(0xffffffffu, m, off));
            float e1 = __expf(x1 - m), e2 = __expf(x2 - m);
            float s = e1 + e2;
            #pragma unroll
            for (int off = 16; off > 0; off >>= 1)
                s += __shfl_xor_sync(0xffffffffu, s, off);
            float inv = 1.f / s;
            L[r * 68 + lane]      = e1 * inv;
            L[r * 68 + 32 + lane] = e2 * inv;
        }
    }
    __syncthreads();

    // ---- sv / sve: thread owns (2c x 2i) output cells ----
    {
        int c0 = (t & 7) * 2;
        int i0 = (t >> 3) * 2;
        float sv00 = 0, sv01 = 0, sv10 = 0, sv11 = 0;
        float se00 = 0, se01 = 0, se10 = 0, se11 = 0;
        #pragma unroll 4
        for (int j = 0; j < 64; j++) {
            float pa = L[i0 * 68 + j];
            float pb = L[(i0 + 1) * 68 + j];
            float va = vT[j * 17 + c0], vb = vT[j * 17 + c0 + 1];
            int d0 = i0 - j + 63;
            float ra = RvT[d0 * 17 + c0],       rb = RvT[d0 * 17 + c0 + 1];
            float rc = RvT[(d0 + 1) * 17 + c0], rd = RvT[(d0 + 1) * 17 + c0 + 1];
            sv00 += pa * va; sv01 += pa * vb;
            sv10 += pb * va; sv11 += pb * vb;
            se00 += pa * ra; se01 += pa * rb;
            se10 += pb * rc; se11 += pb * rd;
        }
        float* op = g_att + (size_t)b * 8192 + (g * 16) * 64;
        float a0 = aes[c0],     o0c = aos[c0],     b0c = bss[c0];
        float a1 = aes[c0 + 1], o1c = aos[c0 + 1], b1c = bss[c0 + 1];
        op[c0 * 64 + i0]           = a0 * sv00 + o0c * se00 + b0c;
        op[c0 * 64 + i0 + 1]       = a0 * sv10 + o0c * se10 + b0c;
        op[(c0 + 1) * 64 + i0]     = a1 * sv01 + o1c * se01 + b1c;
        op[(c0 + 1) * 64 + i0 + 1] = a1 * sv11 + o1c * se11 + b1c;
    }
}

// ---------------- final transpose: att[n][w][q] -> out[n][q][w] -------------
__global__ void tr_out(float* __restrict__ out) {
    __shared__ float tile[32][33];
    int n = blockIdx.z;
    int q0 = blockIdx.y * 32;   // q = p*64 + h  (8192)
    int w0 = blockIdx.x * 32;
    #pragma unroll
    for (int y = threadIdx.y; y < 32; y += 8)
        tile[y][threadIdx.x] =
            g_att[(size_t)(n * 64 + w0 + y) * 8192 + q0 + threadIdx.x];
    __syncthreads();
    #pragma unroll
    for (int y = threadIdx.y; y < 32; y += 8)
        out[(size_t)n * 524288 + (size_t)(q0 + y) * 64 + w0 + threadIdx.x]
            = tile[threadIdx.x][y];
}

// ---------------- launch ----------------
extern "C" void kernel_launch(void* const* d_in, const int* in_sizes, int n_in,
                              void* d_out, int out_size) {
    const float* x    = (const float*)d_in[0];
    const float* wqkv = (const float*)d_in[1];
    const float* rel  = (const float*)d_in[2];
    const float* bnq  = (const float*)d_in[3];
    const float* bns  = (const float*)d_in[4];
    const float* bno  = (const float*)d_in[5];
    float* out = (float*)d_out;

    prep_params<<<1, 256>>>(bnq, bns, bno);
    prep_weff<<<256, 128>>>(wqkv);
    tr_x<<<dim3(2, 2, 2048), dim3(32, 8)>>>(x);
    qkv_gemm<<<1024, 256>>>();
    attn<<<8192, 256>>>(rel);
    tr_out<<<dim3(2, 256, 16), dim3(32, 8)>>>(out);
}

// round 11
// speedup vs baseline: 1.3123x; 1.3123x over previous
#include <cuda_runtime.h>
#include <cuda_bf16.h>
#include <cstdint>

// Problem constants
#define NIMG 16
#define CIN 128
#define HDIM 64
#define WDIM 64
#define BTOT (NIMG*WDIM)      // 1024
#define OQKV 256
#define NGROUP 8
#define BNEPS 1e-5f

// ---------------- scratch ----------------
__device__ __align__(16) float g_xt [BTOT * CIN * HDIM];     // [b][c][h]
__device__ __align__(16) float g_qkv[BTOT * OQKV * HDIM];    // [b][o][h]
__device__ __align__(16) float g_att[BTOT * 128 * HDIM];     // [b][p][h]
__device__ __align__(16) __nv_bfloat16 g_whi[OQKV * CIN];
__device__ __align__(16) __nv_bfloat16 g_wlo[OQKV * CIN];
__device__ float g_bias[OQKV];
__device__ float g_sc  [OQKV];
__device__ float g_aqk[NGROUP], g_aqr[NGROUP], g_akr[NGROUP];
__device__ float g_ae[128], g_ao[128], g_bs[128];

// ---------------- mma.sync helpers (sm_80+ PTX, no 'a'-feature needed) ------
__device__ __forceinline__ uint32_t smem_u32(const void* p) {
    uint32_t a;
    asm("{ .reg .u64 t; cvta.to.shared.u64 t, %1; cvt.u32.u64 %0, t; }" : "=r"(a) : "l"(p));
    return a;
}
__device__ __forceinline__ void ldsm_x4(uint32_t* r, uint32_t addr) {
    asm volatile("ldmatrix.sync.aligned.m8n8.x4.shared.b16 {%0,%1,%2,%3}, [%4];"
                 : "=r"(r[0]), "=r"(r[1]), "=r"(r[2]), "=r"(r[3]) : "r"(addr));
}
__device__ __forceinline__ void mma_bf16(float* c, const uint32_t* a, const uint32_t* b) {
    asm volatile("mma.sync.aligned.m16n8k16.row.col.f32.bf16.bf16.f32 "
                 "{%0,%1,%2,%3}, {%4,%5,%6,%7}, {%8,%9}, {%0,%1,%2,%3};"
                 : "+f"(c[0]), "+f"(c[1]), "+f"(c[2]), "+f"(c[3])
                 : "r"(a[0]), "r"(a[1]), "r"(a[2]), "r"(a[3]), "r"(b[0]), "r"(b[1]));
}

// ---------------- prep ----------------
__global__ void prep_params(const float* __restrict__ bnq,
                            const float* __restrict__ bns,
                            const float* __restrict__ bno) {
    int t = threadIdx.x;
    if (t < 256) {
        float ga = bnq[t], be = bnq[256 + t], m = bnq[512 + t], v = bnq[768 + t];
        float s = ga * rsqrtf(v + BNEPS);
        g_sc[t]  = s;
        g_bias[t] = be - s * m;
    }
    if (t < 24) {
        float s = bns[t] * rsqrtf(bns[72 + t] + BNEPS);
        if (t < 8)       g_aqk[t]      = s;
        else if (t < 16) g_aqr[t - 8]  = s;
        else             g_akr[t - 16] = s;
    }
    if (t < 128) {
        int c0 = 2 * t, c1 = 2 * t + 1;
        float s0 = bno[c0] * rsqrtf(bno[768 + c0] + BNEPS);
        float s1 = bno[c1] * rsqrtf(bno[768 + c1] + BNEPS);
        g_ae[t] = s0;
        g_ao[t] = s1;
        g_bs[t] = (bno[256 + c0] - s0 * bno[512 + c0])
                + (bno[256 + c1] - s1 * bno[512 + c1]);
    }
}

__global__ void prep_wsplit(const float* __restrict__ w) {
    int o = blockIdx.x, k = threadIdx.x;
    float we = w[o * 128 + k] * g_sc[o];
    __nv_bfloat16 hi = __float2bfloat16_rn(we);
    g_whi[o * 128 + k] = hi;
    g_wlo[o * 128 + k] = __float2bfloat16_rn(we - __bfloat162float(hi));
}

// ---------------- transpose x: (n,c,h,w) -> xt[b=(n,w)][c][h] ----------------
__global__ void tr_x(const float* __restrict__ x) {
    __shared__ float tile[32][33];
    int nc = blockIdx.z;
    int n = nc >> 7, c = nc & 127;
    int h0 = blockIdx.x * 32, w0 = blockIdx.y * 32;
    const float* src = x + ((size_t)(n * 128 + c)) * 4096;
    #pragma unroll
    for (int y = threadIdx.y; y < 32; y += 8)
        tile[y][threadIdx.x] = src[(h0 + y) * 64 + w0 + threadIdx.x];
    __syncthreads();
    #pragma unroll
    for (int y = threadIdx.y; y < 32; y += 8)
        g_xt[((size_t)((n * 64 + (w0 + y)) * 128 + c)) * 64 + h0 + threadIdx.x]
            = tile[threadIdx.x][y];
}

// ---------------- QKV GEMM via mma.sync bf16 (hi/lo x3 split) ---------------
#define LDW 136
#define SM_WHI 0
#define SM_WLO (SM_WHI + OQKV * LDW * 2)          // 69632
#define SM_XHI (SM_WLO + OQKV * LDW * 2)          // 139264
#define SM_XLO (SM_XHI + HDIM * LDW * 2)          // 156672
#define SM_TOTAL (SM_XLO + HDIM * LDW * 2)        // 174080

__global__ void __launch_bounds__(256, 1) qkv_mma() {
    extern __shared__ __align__(16) char smem[];
    uint32_t sb = smem_u32(smem);
    int t = threadIdx.x;
    int wid = t >> 5, lane = t & 31;

    // ---- stage W hi/lo (float4 = 8 bf16) ----
    {
        const float4* whi = (const float4*)g_whi;
        const float4* wlo = (const float4*)g_wlo;
        #pragma unroll
        for (int i = 0; i < 16; i++) {
            int idx = t + i * 256;          // 4096 float4s
            int o = idx >> 4, c4 = idx & 15;
            *(float4*)(smem + SM_WHI + o * (LDW * 2) + c4 * 16) = whi[idx];
            *(float4*)(smem + SM_WLO + o * (LDW * 2) + c4 * 16) = wlo[idx];
        }
    }

    // ldmatrix addresses (constant per thread)
    // A (row-major [o][k]): mat quadrants r0-7/r8-15 x k0-7/k8-15
    uint32_t a_row = (uint32_t)(wid * 32) + (lane & 15);
    uint32_t a_off = a_row * (LDW * 2) + ((lane >> 4) << 3) * 2;
    // B (col-major = [n=h][k] row-major): NON-trans ldmatrix.
    // mats: (h0-7,k0-7),(h0-7,k8-15),(h8-15,k0-7),(h8-15,k8-15)
    uint32_t b_row = ((lane >> 4) << 3) + (lane & 7);
    uint32_t b_off = b_row * (LDW * 2) + (((lane >> 3) & 1) << 3) * 2;

    float bias_lo[2], bias_hi[2];
    #pragma unroll
    for (int mt = 0; mt < 2; mt++) {
        int o = wid * 32 + mt * 16 + (lane >> 2);
        bias_lo[mt] = g_bias[o];
        bias_hi[mt] = g_bias[o + 8];
    }

    for (int b = blockIdx.x; b < BTOT; b += gridDim.x) {
        __syncthreads();   // protect X buffers from previous iteration's readers

        // ---- convert X[b] fp32 [c][h] -> bf16 hi/lo transposed [h][c] ----
        const float* xb = g_xt + (size_t)b * 8192;
        #pragma unroll
        for (int i = 0; i < 32; i++) {
            int idx = t + i * 256;
            int c = idx >> 6, h = idx & 63;
            float v = xb[idx];
            __nv_bfloat16 hi = __float2bfloat16_rn(v);
            __nv_bfloat16 lo = __float2bfloat16_rn(v - __bfloat162float(hi));
            uint32_t off = (uint32_t)h * (LDW * 2) + (uint32_t)c * 2;
            *(__nv_bfloat16*)(smem + SM_XHI + off) = hi;
            *(__nv_bfloat16*)(smem + SM_XLO + off) = lo;
        }
        __syncthreads();

        float acc[2][8][4];
        #pragma unroll
        for (int mt = 0; mt < 2; mt++)
            #pragma unroll
            for (int nt = 0; nt < 8; nt++)
                #pragma unroll
                for (int q = 0; q < 4; q++) acc[mt][nt][q] = 0.f;

        #pragma unroll
        for (int k = 0; k < 8; k++) {
            uint32_t kb = (uint32_t)k * 32;   // k*16 elems * 2B
            uint32_t Ahi[2][4], Alo[2][4], Bhi[4][4], Blo[4][4];
            #pragma unroll
            for (int mt = 0; mt < 2; mt++) {
                uint32_t ao = a_off + (uint32_t)mt * 16 * (LDW * 2) + kb;
                ldsm_x4(Ahi[mt], sb + SM_WHI + ao);
                ldsm_x4(Alo[mt], sb + SM_WLO + ao);
            }
            #pragma unroll
            for (int nt2 = 0; nt2 < 4; nt2++) {
                uint32_t bo = b_off + (uint32_t)nt2 * 16 * (LDW * 2) + kb;
                ldsm_x4(Bhi[nt2], sb + SM_XHI + bo);
                ldsm_x4(Blo[nt2], sb + SM_XLO + bo);
            }
            #pragma unroll
            for (int mt = 0; mt < 2; mt++)
                #pragma unroll
                for (int nt2 = 0; nt2 < 4; nt2++) {
                    mma_bf16(acc[mt][2 * nt2],     Ahi[mt], &Bhi[nt2][0]);
                    mma_bf16(acc[mt][2 * nt2],     Ahi[mt], &Blo[nt2][0]);
                    mma_bf16(acc[mt][2 * nt2],     Alo[mt], &Bhi[nt2][0]);
                    mma_bf16(acc[mt][2 * nt2 + 1], Ahi[mt], &Bhi[nt2][2]);
                    mma_bf16(acc[mt][2 * nt2 + 1], Ahi[mt], &Blo[nt2][2]);
                    mma_bf16(acc[mt][2 * nt2 + 1], Alo[mt], &Bhi[nt2][2]);
                }
        }

        // ---- epilogue: D + bias -> g_qkv[b][o][h] ----
        float* op = g_qkv + (size_t)b * 16384;
        #pragma unroll
        for (int mt = 0; mt < 2; mt++) {
            int o = wid * 32 + mt * 16 + (lane >> 2);
            #pragma unroll
            for (int nt = 0; nt < 8; nt++) {
                int h = nt * 8 + 2 * (lane & 3);
                float2 r0, r1;
                r0.x = acc[mt][nt][0] + bias_lo[mt];
                r0.y = acc[mt][nt][1] + bias_lo[mt];
                r1.x = acc[mt][nt][2] + bias_hi[mt];
                r1.y = acc[mt][nt][3] + bias_hi[mt];
                *(float2*)&op[o * 64 + h]       = r0;
                *(float2*)&op[(o + 8) * 64 + h] = r1;
            }
        }
    }
}

// ---------------- attention per (b, g) ----------------
__global__ void __launch_bounds__(256) attn(const float* __restrict__ rel) {
    int bx = blockIdx.x;
    int g = bx & 7;
    int b = bx >> 3;

    __shared__ __align__(16) float qs[8 * 64];
    __shared__ __align__(16) float ks[8 * 64];
    __shared__ __align__(16) float vT[64 * 17];
    __shared__ __align__(16) float Rq[8 * 128];
    __shared__ __align__(16) float Rk[8 * 128];
    __shared__ __align__(16) float RvT[127 * 17];
    __shared__ __align__(16) float L[64 * 68];
    __shared__ float aes[16], aos[16], bss[16];

    int t = threadIdx.x;
    float aqk = g_aqk[g];
    float rqs = g_aqr[g] / aqk;
    float akr = g_akr[g];

    const float* qkvb = g_qkv + (size_t)b * 16384 + g * 32 * 64;

    for (int idx = t; idx < 1024; idx += 256) {
        int c = idx >> 6, h = idx & 63;
        float val = qkvb[idx];
        if (c < 8) qs[c * 64 + h] = val * aqk;
        else       ks[(c - 8) * 64 + h] = val;
    }
    for (int idx = t; idx < 1024; idx += 256) {
        int c = idx >> 6, h = idx & 63;
        vT[h * 17 + c] = qkvb[1024 + idx];
    }
    for (int idx = t; idx < 1016; idx += 256) {
        int c = idx / 127, d = idx % 127;
        Rq[c * 128 + d] = rel[c * 127 + d] * rqs;
        Rk[c * 128 + d] = rel[(8 + c) * 127 + d] * akr;
    }
    for (int idx = t; idx < 2032; idx += 256) {
        int c = idx / 127, d = idx % 127;
        RvT[d * 17 + c] = rel[(16 + c) * 127 + d];
    }
    if (t < 16) {
        int p = g * 16 + t;
        aes[t] = g_ae[p]; aos[t] = g_ao[p]; bss[t] = g_bs[p];
    }
    __syncthreads();

    {
        int ti = t & 15, tj = t >> 4;
        int i0 = ti * 4, j0 = tj * 4;
        int dbase = i0 - j0 + 60;
        int ebase = j0 - i0 + 60;
        float acc[4][4];
        #pragma unroll
        for (int a = 0; a < 4; a++)
            #pragma unroll
            for (int bb = 0; bb < 4; bb++) acc[a][bb] = 0.f;

        #pragma unroll
        for (int c = 0; c < 8; c++) {
            float qv[4], kv[4], rq[7], rk[7];
            #pragma unroll
            for (int ii = 0; ii < 4; ii++) qv[ii] = qs[c * 64 + i0 + ii];
            #pragma unroll
            for (int jj = 0; jj < 4; jj++) kv[jj] = ks[c * 64 + j0 + jj];
            #pragma unroll
            for (int x = 0; x < 7; x++) rq[x] = Rq[c * 128 + dbase + x];
            #pragma unroll
            for (int x = 0; x < 7; x++) rk[x] = Rk[c * 128 + ebase + x];
            #pragma unroll
            for (int ii = 0; ii < 4; ii++)
                #pragma unroll
                for (int jj = 0; jj < 4; jj++)
                    acc[ii][jj] += qv[ii] * (kv[jj] + rq[ii - jj + 3])
                                 + kv[jj] * rk[jj - ii + 3];
        }
        #pragma unroll
        for (int ii = 0; ii < 4; ii++) {
            float4 r;
            r.x = acc[ii][0]; r.y = acc[ii][1]; r.z = acc[ii][2]; r.w = acc[ii][3];
            *(float4*)&L[(i0 + ii) * 68 + j0] = r;
        }
    }
    __syncthreads();

    {
        int w = t >> 5, lane = t & 31;
        for (int r = w * 8; r < w * 8 + 8; r++) {
            float x1 = L[r * 68 + lane], x2 = L[r * 68 + 32 + lane];
            float m = fmaxf(x1, x2);
            #pragma unroll
            for (int off = 16; off > 0; off >>= 1)
                m = fmaxf(m, __shfl_xor_sync(0xffffffffu, m, off));
            float e1 = __expf(x1 - m), e2 = __expf(x2 - m);
            float s = e1 + e2;
            #pragma unroll
            for (int off = 16; off > 0; off >>= 1)
                s += __shfl_xor_sync(0xffffffffu, s, off);
            float inv = 1.f / s;
            L[r * 68 + lane]      = e1 * inv;
            L[r * 68 + 32 + lane] = e2 * inv;
        }
    }
    __syncthreads();

    {
        int c0 = (t & 7) * 2;
        int i0 = (t >> 3) * 2;
        float sv00 = 0, sv01 = 0, sv10 = 0, sv11 = 0;
        float se00 = 0, se01 = 0, se10 = 0, se11 = 0;
        #pragma unroll 4
        for (int j = 0; j < 64; j++) {
            float pa = L[i0 * 68 + j];
            float pb = L[(i0 + 1) * 68 + j];
            float va = vT[j * 17 + c0], vb = vT[j * 17 + c0 + 1];
            int d0 = i0 - j + 63;
            float ra = RvT[d0 * 17 + c0],       rb = RvT[d0 * 17 + c0 + 1];
            float rc = RvT[(d0 + 1) * 17 + c0], rd = RvT[(d0 + 1) * 17 + c0 + 1];
            sv00 += pa * va; sv01 += pa * vb;
            sv10 += pb * va; sv11 += pb * vb;
            se00 += pa * ra; se01 += pa * rb;
            se10 += pb * rc; se11 += pb * rd;
        }
        float* op = g_att + (size_t)b * 8192 + (g * 16) * 64;
        float a0 = aes[c0],     o0c = aos[c0],     b0c = bss[c0];
        float a1 = aes[c0 + 1], o1c = aos[c0 + 1], b1c = bss[c0 + 1];
        op[c0 * 64 + i0]           = a0 * sv00 + o0c * se00 + b0c;
        op[c0 * 64 + i0 + 1]       = a0 * sv10 + o0c * se10 + b0c;
        op[(c0 + 1) * 64 + i0]     = a1 * sv01 + o1c * se01 + b1c;
        op[(c0 + 1) * 64 + i0 + 1] = a1 * sv11 + o1c * se11 + b1c;
    }
}

// ---------------- final transpose ----------------
__global__ void tr_out(float* __restrict__ out) {
    __shared__ float tile[32][33];
    int n = blockIdx.z;
    int q0 = blockIdx.y * 32;
    int w0 = blockIdx.x * 32;
    #pragma unroll
    for (int y = threadIdx.y; y < 32; y += 8)
        tile[y][threadIdx.x] =
            g_att[(size_t)(n * 64 + w0 + y) * 8192 + q0 + threadIdx.x];
    __syncthreads();
    #pragma unroll
    for (int y = threadIdx.y; y < 32; y += 8)
        out[(size_t)n * 524288 + (size_t)(q0 + y) * 64 + w0 + threadIdx.x]
            = tile[threadIdx.x][y];
}

// ---------------- launch ----------------
extern "C" void kernel_launch(void* const* d_in, const int* in_sizes, int n_in,
                              void* d_out, int out_size) {
    const float* x    = (const float*)d_in[0];
    const float* wqkv = (const float*)d_in[1];
    const float* rel  = (const float*)d_in[2];
    const float* bnq  = (const float*)d_in[3];
    const float* bns  = (const float*)d_in[4];
    const float* bno  = (const float*)d_in[5];
    float* out = (float*)d_out;

    cudaFuncSetAttribute(qkv_mma, cudaFuncAttributeMaxDynamicSharedMemorySize, SM_TOTAL);

    prep_params<<<1, 256>>>(bnq, bns, bno);
    prep_wsplit<<<256, 128>>>(wqkv);
    tr_x<<<dim3(2, 2, 2048), dim3(32, 8)>>>(x);
    qkv_mma<<<148, 256, SM_TOTAL>>>();
    attn<<<8192, 256>>>(rel);
    tr_out<<<dim3(2, 256, 16), dim3(32, 8)>>>(out);
}